// round 1
// baseline (speedup 1.0000x reference)
#include <cuda_runtime.h>

#define NN 40000
#define EE 640000
#define GG 2048
#define DD 128
#define LL 5

// ---------------- device scratch (static, allocation-free) ----------------
__device__ float g_X[NN * DD];        // node features (layer input/output)
__device__ float g_H[NN * DD];        // (1+eps)*x + aggregated messages
__device__ float g_M[NN * 2 * DD];    // MLP intermediate (N x 256)
__device__ float g_etab[512 * DD];    // per-layer bond-embedding table (8^3 codes)
__device__ int   g_rowptr[NN + 1];
__device__ int   g_deg[NN];
__device__ int   g_cursor[NN];
__device__ int   g_csr[EE];           // packed: src (16b) | code (9b) << 16

// ---------------- CSR construction ----------------
__global__ void k_zero() {
    int i = blockIdx.x * blockDim.x + threadIdx.x;
    if (i < NN) { g_deg[i] = 0; g_cursor[i] = 0; }
}

__global__ void k_count(const int* __restrict__ eidx) {
    int e = blockIdx.x * blockDim.x + threadIdx.x;
    if (e < EE) atomicAdd(&g_deg[eidx[EE + e]], 1);
}

__global__ void k_scan() {
    __shared__ int warp_sums[32];
    __shared__ int s_carry;
    int tid = threadIdx.x;
    if (tid == 0) { s_carry = 0; g_rowptr[0] = 0; }
    __syncthreads();
    int lane = tid & 31, w = tid >> 5;
    for (int base = 0; base < NN; base += 1024) {
        int i = base + tid;
        int v = (i < NN) ? g_deg[i] : 0;
        int x = v;
        #pragma unroll
        for (int o = 1; o < 32; o <<= 1) {
            int y = __shfl_up_sync(0xFFFFFFFFu, x, o);
            if (lane >= o) x += y;
        }
        if (lane == 31) warp_sums[w] = x;
        __syncthreads();
        if (w == 0) {
            int s = warp_sums[lane];
            #pragma unroll
            for (int o = 1; o < 32; o <<= 1) {
                int y = __shfl_up_sync(0xFFFFFFFFu, s, o);
                if (lane >= o) s += y;
            }
            warp_sums[lane] = s;
        }
        __syncthreads();
        int incl = x + (w > 0 ? warp_sums[w - 1] : 0) + s_carry;
        if (i < NN) g_rowptr[i + 1] = incl;
        __syncthreads();
        if (tid == 1023) s_carry = incl;
        __syncthreads();
    }
}

__global__ void k_fill(const int* __restrict__ eidx, const int* __restrict__ eattr) {
    int e = blockIdx.x * blockDim.x + threadIdx.x;
    if (e < EE) {
        int d = eidx[EE + e];
        int pos = atomicAdd(&g_cursor[d], 1);
        int s = eidx[e];
        int code = eattr[e * 3] | (eattr[e * 3 + 1] << 3) | (eattr[e * 3 + 2] << 6);
        g_csr[g_rowptr[d] + pos] = s | (code << 16);
    }
}

// ---------------- atom encoder ----------------
__global__ void k_atom(const int* __restrict__ xa, const float* __restrict__ aemb) {
    int node = blockIdx.x * 2 + (threadIdx.x >> 7);
    int d = threadIdx.x & 127;
    float s = 0.f;
    #pragma unroll
    for (int f = 0; f < 9; ++f) {
        int idx = xa[node * 9 + f];
        s += aemb[(f * 64 + idx) * DD + d];
    }
    g_X[node * DD + d] = s;
}

// ---------------- bond-embedding code table (per layer) ----------------
__global__ void k_etab(const float* __restrict__ bemb) {
    int c = blockIdx.x;
    int d = threadIdx.x;
    float s = 0.f;
    #pragma unroll
    for (int f = 0; f < 3; ++f) {
        int idx = (c >> (3 * f)) & 7;
        s += bemb[(f * 8 + idx) * DD + d];
    }
    g_etab[c * DD + d] = s;
}

// ---------------- aggregate: warp per node, atomic-free ----------------
__global__ void k_agg(const float* __restrict__ epsv, int layer) {
    int node = blockIdx.x * 8 + (threadIdx.x >> 5);
    int l = threadIdx.x & 31;
    const float4* __restrict__ X4 = (const float4*)g_X;
    const float4* __restrict__ E4 = (const float4*)g_etab;
    float eps1 = 1.f + epsv[layer];
    float4 xv = X4[node * 32 + l];
    float4 acc = make_float4(xv.x * eps1, xv.y * eps1, xv.z * eps1, xv.w * eps1);
    int beg = g_rowptr[node], end = g_rowptr[node + 1];
    for (int j = beg; j < end; ++j) {
        int p = g_csr[j];
        int s = p & 0xFFFF;
        int c = p >> 16;
        float4 a = X4[s * 32 + l];
        float4 b = E4[c * 32 + l];
        acc.x += fmaxf(a.x + b.x, 0.f);
        acc.y += fmaxf(a.y + b.y, 0.f);
        acc.z += fmaxf(a.z + b.z, 0.f);
        acc.w += fmaxf(a.w + b.w, 0.f);
    }
    ((float4*)g_H)[node * 32 + l] = acc;
}

// ---------------- tiled SGEMM + fused bias/BN/ReLU epilogue ----------------
// C[M x ncols] = epilogue(A[M x K] @ W[K x ncols])
// block: 128x128 tile, 256 threads, 8x8 micro-tile, BK=32
__global__ void __launch_bounds__(256) k_gemm(
    int asel, int osel,
    const float* __restrict__ W,
    const float* __restrict__ bias,
    const float* __restrict__ bng, const float* __restrict__ bnb,
    const float* __restrict__ bnm, const float* __restrict__ bnv,
    int K, int ncols, int relu_flag)
{
    const float* __restrict__ A = asel ? g_M : g_H;
    float* __restrict__ Out = osel ? g_X : g_M;

    __shared__ float As[32 * 129];   // transposed [k][m], +1 pad
    __shared__ float Bs[32 * 128];   // [k][n]

    int tid = threadIdx.x;
    int tx = tid & 15;       // 0..15 (col group)
    int ty = tid >> 4;       // 0..15 (row group)
    int m0 = blockIdx.x * 128;
    int n0 = blockIdx.y * 128;

    float acc[8][8];
    #pragma unroll
    for (int i = 0; i < 8; ++i)
        #pragma unroll
        for (int j = 0; j < 8; ++j) acc[i][j] = 0.f;

    int arow = tid >> 5;     // 0..7
    int akk  = tid & 31;     // 0..31

    for (int k0 = 0; k0 < K; k0 += 32) {
        // A tile: 128 rows x 32 k, stored transposed (conflict-free: bank = akk)
        #pragma unroll
        for (int p = 0; p < 16; ++p) {
            int r = arow + p * 8;
            int gr = m0 + r;
            As[akk * 129 + r] = (gr < NN) ? A[(size_t)gr * K + k0 + akk] : 0.f;
        }
        // W tile: 32 k x 128 n, float4 coalesced
        #pragma unroll
        for (int p = 0; p < 4; ++p) {
            int kr = arow + p * 8;
            float4 v = *(const float4*)(W + (size_t)(k0 + kr) * ncols + n0 + akk * 4);
            *(float4*)(&Bs[kr * 128 + akk * 4]) = v;
        }
        __syncthreads();
        #pragma unroll
        for (int k = 0; k < 32; ++k) {
            float a[8], b[8];
            #pragma unroll
            for (int i = 0; i < 8; ++i) a[i] = As[k * 129 + ty * 8 + i];
            #pragma unroll
            for (int j = 0; j < 8; ++j) b[j] = Bs[k * 128 + tx + 16 * j];
            #pragma unroll
            for (int i = 0; i < 8; ++i)
                #pragma unroll
                for (int j = 0; j < 8; ++j)
                    acc[i][j] = fmaf(a[i], b[j], acc[i][j]);
        }
        __syncthreads();
    }

    // epilogue: y = ((acc + bias) - m) * g * rsqrt(v+eps) + b, optional relu
    float sc[8], sh[8], bi[8];
    #pragma unroll
    for (int j = 0; j < 8; ++j) {
        int c = n0 + tx + 16 * j;
        float s = bng[c] * rsqrtf(bnv[c] + 1e-5f);
        sc[j] = s;
        sh[j] = bnb[c] - bnm[c] * s;
        bi[j] = bias[c];
    }
    #pragma unroll
    for (int i = 0; i < 8; ++i) {
        int gr = m0 + ty * 8 + i;
        if (gr < NN) {
            #pragma unroll
            for (int j = 0; j < 8; ++j) {
                float v = (acc[i][j] + bi[j]) * sc[j] + sh[j];
                if (relu_flag) v = fmaxf(v, 0.f);
                Out[(size_t)gr * ncols + n0 + tx + 16 * j] = v;
            }
        }
    }
}

// ---------------- pooling + head (batch sorted -> binary search) ----------------
__device__ __forceinline__ int lb(const int* a, int n, int v) {
    int lo = 0, hi = n;
    while (lo < hi) { int m = (lo + hi) >> 1; if (a[m] < v) lo = m + 1; else hi = m; }
    return lo;
}

__global__ void k_pool(const int* __restrict__ batch,
                       const float* __restrict__ Wp, const float* __restrict__ bp,
                       float* __restrict__ out)
{
    int g = blockIdx.x;
    int lo = lb(batch, NN, g);
    int hi = lb(batch, NN, g + 1);
    int d = threadIdx.x;  // 128
    float s = 0.f;
    for (int n = lo; n < hi; ++n) s += g_X[n * DD + d];
    s /= fmaxf((float)(hi - lo), 1.f);
    __shared__ float pooled[DD];
    pooled[d] = s;
    __syncthreads();
    if (d < 10) {
        float o = bp[d];
        #pragma unroll 4
        for (int k = 0; k < DD; ++k) o += pooled[k] * Wp[k * 10 + d];
        out[g * 10 + d] = o;
    }
}

// ---------------- launch ----------------
extern "C" void kernel_launch(void* const* d_in, const int* in_sizes, int n_in,
                              void* d_out, int out_size)
{
    const int*   x_atom = (const int*)d_in[0];
    const int*   eidx   = (const int*)d_in[1];
    const int*   eattr  = (const int*)d_in[2];
    const int*   batch  = (const int*)d_in[3];
    const float* aemb   = (const float*)d_in[4];
    const float* bemb   = (const float*)d_in[5];
    const float* eps    = (const float*)d_in[6];
    const float* W1     = (const float*)d_in[7];
    const float* b1     = (const float*)d_in[8];
    const float* g1     = (const float*)d_in[9];
    const float* bt1    = (const float*)d_in[10];
    const float* m1     = (const float*)d_in[11];
    const float* v1     = (const float*)d_in[12];
    const float* W2     = (const float*)d_in[13];
    const float* b2     = (const float*)d_in[14];
    const float* gO     = (const float*)d_in[15];
    const float* btO    = (const float*)d_in[16];
    const float* mO     = (const float*)d_in[17];
    const float* vO     = (const float*)d_in[18];
    const float* Wp     = (const float*)d_in[19];
    const float* bp     = (const float*)d_in[20];
    float* out = (float*)d_out;

    // CSR build (edge structure is launch-invariant but rebuilt each call: deterministic work)
    k_zero<<<(NN + 255) / 256, 256>>>();
    k_count<<<(EE + 255) / 256, 256>>>(eidx);
    k_scan<<<1, 1024>>>();
    k_fill<<<(EE + 255) / 256, 256>>>(eidx, eattr);
    k_atom<<<NN / 2, 256>>>(x_atom, aemb);

    for (int i = 0; i < LL; ++i) {
        k_etab<<<512, 128>>>(bemb + (size_t)i * 3 * 8 * DD);
        k_agg<<<NN / 8, 256>>>(eps, i);
        dim3 grid1((NN + 127) / 128, 2);
        k_gemm<<<grid1, 256>>>(0, 0,
            W1 + (size_t)i * DD * 2 * DD, b1 + i * 2 * DD,
            g1 + i * 2 * DD, bt1 + i * 2 * DD, m1 + i * 2 * DD, v1 + i * 2 * DD,
            DD, 2 * DD, 1);
        dim3 grid2((NN + 127) / 128, 1);
        k_gemm<<<grid2, 256>>>(1, 1,
            W2 + (size_t)i * 2 * DD * DD, b2 + i * DD,
            gO + i * DD, btO + i * DD, mO + i * DD, vO + i * DD,
            2 * DD, DD, (i < LL - 1) ? 1 : 0);
    }

    k_pool<<<GG, 128>>>(batch, Wp, bp, out);
}

// round 3
// speedup vs baseline: 1.8530x; 1.8530x over previous
#include <cuda_runtime.h>
#include <cuda_bf16.h>
#include <cstdint>

#define NN 40000
#define EE 640000
#define GG 2048
#define DD 128
#define LL 5

// ================= warp MMA helpers (base-target sm_80+ path) =================
__device__ __forceinline__ uint32_t smem_u32(const void* p) {
    uint32_t a;
    asm("{ .reg .u64 t; cvta.to.shared.u64 t, %1; cvt.u32.u64 %0, t; }" : "=r"(a) : "l"(p));
    return a;
}
__device__ __forceinline__ void ldsm_x4(uint32_t addr, uint32_t& r0, uint32_t& r1,
                                        uint32_t& r2, uint32_t& r3) {
    asm volatile("ldmatrix.sync.aligned.m8n8.x4.shared.b16 {%0,%1,%2,%3}, [%4];"
                 : "=r"(r0), "=r"(r1), "=r"(r2), "=r"(r3) : "r"(addr));
}
__device__ __forceinline__ void mma16816(float* d, const uint32_t* a, const uint32_t* b) {
    asm volatile(
        "mma.sync.aligned.m16n8k16.row.col.f32.bf16.bf16.f32 "
        "{%0,%1,%2,%3}, {%4,%5,%6,%7}, {%8,%9}, {%0,%1,%2,%3};"
        : "+f"(d[0]), "+f"(d[1]), "+f"(d[2]), "+f"(d[3])
        : "r"(a[0]), "r"(a[1]), "r"(a[2]), "r"(a[3]), "r"(b[0]), "r"(b[1]));
}

// ================= device scratch =================
__device__ float          g_X[NN * DD];          // fp32 node features (agg input / pool)
__device__ __nv_bfloat16  g_Hh[NN * DD];         // GEMM1 input hi
__device__ __nv_bfloat16  g_Hl[NN * DD];         // GEMM1 input lo
__device__ __nv_bfloat16  g_Mh[NN * 2 * DD];     // GEMM2 input hi
__device__ __nv_bfloat16  g_Ml[NN * 2 * DD];     // GEMM2 input lo
__device__ float          g_etab[512 * DD];
__device__ int            g_rowptr[NN + 1];
__device__ int            g_deg[NN];
__device__ int            g_cursor[NN];
__device__ int            g_csr[EE];
// weight images, hi/lo split, [n][k] row-major per 128x128 tile:
// g_w1s[layer][ntile(2)][hi/lo(2)][128*128], g_w2s[layer][kchunk(2)][hi/lo(2)][128*128]
__device__ __nv_bfloat16  g_w1s[LL * 2 * 2 * 16384];
__device__ __nv_bfloat16  g_w2s[LL * 2 * 2 * 16384];

// ================= CSR construction =================
__global__ void k_zero() {
    int i = blockIdx.x * blockDim.x + threadIdx.x;
    if (i < NN) { g_deg[i] = 0; g_cursor[i] = 0; }
}
__global__ void k_count(const int* __restrict__ eidx) {
    int e = blockIdx.x * blockDim.x + threadIdx.x;
    if (e < EE) atomicAdd(&g_deg[eidx[EE + e]], 1);
}
__global__ void k_scan() {
    __shared__ int warp_sums[32];
    __shared__ int s_carry;
    int tid = threadIdx.x;
    if (tid == 0) { s_carry = 0; g_rowptr[0] = 0; }
    __syncthreads();
    int lane = tid & 31, w = tid >> 5;
    for (int base = 0; base < NN; base += 1024) {
        int i = base + tid;
        int v = (i < NN) ? g_deg[i] : 0;
        int x = v;
        #pragma unroll
        for (int o = 1; o < 32; o <<= 1) {
            int y = __shfl_up_sync(0xFFFFFFFFu, x, o);
            if (lane >= o) x += y;
        }
        if (lane == 31) warp_sums[w] = x;
        __syncthreads();
        if (w == 0) {
            int s = warp_sums[lane];
            #pragma unroll
            for (int o = 1; o < 32; o <<= 1) {
                int y = __shfl_up_sync(0xFFFFFFFFu, s, o);
                if (lane >= o) s += y;
            }
            warp_sums[lane] = s;
        }
        __syncthreads();
        int incl = x + (w > 0 ? warp_sums[w - 1] : 0) + s_carry;
        if (i < NN) g_rowptr[i + 1] = incl;
        __syncthreads();
        if (tid == 1023) s_carry = incl;
        __syncthreads();
    }
}
__global__ void k_fill(const int* __restrict__ eidx, const int* __restrict__ eattr) {
    int e = blockIdx.x * blockDim.x + threadIdx.x;
    if (e < EE) {
        int d = eidx[EE + e];
        int pos = atomicAdd(&g_cursor[d], 1);
        int s = eidx[e];
        int code = eattr[e * 3] | (eattr[e * 3 + 1] << 3) | (eattr[e * 3 + 2] << 6);
        g_csr[g_rowptr[d] + pos] = s | (code << 16);
    }
}

// ================= atom encoder =================
__global__ void k_atom(const int* __restrict__ xa, const float* __restrict__ aemb) {
    int node = blockIdx.x * 2 + (threadIdx.x >> 7);
    int d = threadIdx.x & 127;
    float s = 0.f;
    #pragma unroll
    for (int f = 0; f < 9; ++f) {
        int idx = xa[node * 9 + f];
        s += aemb[(f * 64 + idx) * DD + d];
    }
    g_X[node * DD + d] = s;
}

// ================= bond-embedding code table =================
__global__ void k_etab(const float* __restrict__ bemb) {
    int c = blockIdx.x;
    int d = threadIdx.x;
    float s = 0.f;
    #pragma unroll
    for (int f = 0; f < 3; ++f) {
        int idx = (c >> (3 * f)) & 7;
        s += bemb[(f * 8 + idx) * DD + d];
    }
    g_etab[c * DD + d] = s;
}

// ================= weight split + transpose (bf16 hi/lo) =================
// W1 [L][128][256] -> per (layer, ntile t): B[n][k] = W1[l][k][t*128+n]
__global__ void k_wconv1(const float* __restrict__ W1) {
    int idx = blockIdx.x * 256 + threadIdx.x;           // L*2*16384
    int e = idx & 16383, t = (idx >> 14) & 1, l = idx >> 15;
    int n = e >> 7, k = e & 127;
    float v = W1[((size_t)l * 128 + k) * 256 + t * 128 + n];
    __nv_bfloat16 hi = __float2bfloat16(v);
    __nv_bfloat16 lo = __float2bfloat16(v - __bfloat162float(hi));
    size_t base = ((size_t)(l * 2 + t) * 2) << 14;
    g_w1s[base + n * 128 + k] = hi;
    g_w1s[base + 16384 + n * 128 + k] = lo;
}
// W2 [L][256][128] -> per (layer, kchunk c): B[n][kk] = W2[l][c*128+kk][n]
__global__ void k_wconv2(const float* __restrict__ W2) {
    int idx = blockIdx.x * 256 + threadIdx.x;
    int e = idx & 16383, c = (idx >> 14) & 1, l = idx >> 15;
    int n = e >> 7, kk = e & 127;
    float v = W2[((size_t)l * 256 + c * 128 + kk) * 128 + n];
    __nv_bfloat16 hi = __float2bfloat16(v);
    __nv_bfloat16 lo = __float2bfloat16(v - __bfloat162float(hi));
    size_t base = ((size_t)(l * 2 + c) * 2) << 14;
    g_w2s[base + n * 128 + kk] = hi;
    g_w2s[base + 16384 + n * 128 + kk] = lo;
}

// ================= aggregate: warp/node, atomic-free, emits bf16 hi/lo ======
__global__ void k_agg(const float* __restrict__ epsv, int layer) {
    int node = blockIdx.x * 8 + (threadIdx.x >> 5);
    int l = threadIdx.x & 31;
    const float4* __restrict__ X4 = (const float4*)g_X;
    const float4* __restrict__ E4 = (const float4*)g_etab;
    float eps1 = 1.f + epsv[layer];
    float4 xv = X4[node * 32 + l];
    float4 acc = make_float4(xv.x * eps1, xv.y * eps1, xv.z * eps1, xv.w * eps1);
    int beg = g_rowptr[node], end = g_rowptr[node + 1];
    for (int j = beg; j < end; ++j) {
        int p = g_csr[j];
        int s = p & 0xFFFF;
        int c = p >> 16;
        float4 a = X4[s * 32 + l];
        float4 b = E4[c * 32 + l];
        acc.x += fmaxf(a.x + b.x, 0.f);
        acc.y += fmaxf(a.y + b.y, 0.f);
        acc.z += fmaxf(a.z + b.z, 0.f);
        acc.w += fmaxf(a.w + b.w, 0.f);
    }
    float vv[4] = {acc.x, acc.y, acc.z, acc.w};
    __nv_bfloat16 h[4], lo[4];
    #pragma unroll
    for (int q = 0; q < 4; ++q) {
        h[q] = __float2bfloat16(vv[q]);
        lo[q] = __float2bfloat16(vv[q] - __bfloat162float(h[q]));
    }
    size_t base = (size_t)node * DD + l * 4;
    *(__nv_bfloat162*)(g_Hh + base)     = __nv_bfloat162(h[0], h[1]);
    *(__nv_bfloat162*)(g_Hh + base + 2) = __nv_bfloat162(h[2], h[3]);
    *(__nv_bfloat162*)(g_Hl + base)     = __nv_bfloat162(lo[0], lo[1]);
    *(__nv_bfloat162*)(g_Hl + base + 2) = __nv_bfloat162(lo[2], lo[3]);
}

// ================= HMMA GEMM: 128x128 tile, bf16 hi/lo 3-term split =========
// which==0: g_H(h/l)[Nx128] @ W1tile -> g_M(h/l)[Nx256], relu always
// which==1: g_M(h/l)[Nx256] @ W2 -> g_X f32 [Nx128], relu if flag
// SMEM tiles: 128 rows x 128 k bf16, row stride 256B, 16B chunks XOR-swizzled:
// off(r,c8) = r*256 + ((c8 ^ (r&7)) << 4)   -> conflict-free ldmatrix
__global__ void __launch_bounds__(256, 1) k_gemm_mma(
    int which, int layer,
    const float* __restrict__ bias,
    const float* __restrict__ bng, const float* __restrict__ bnb,
    const float* __restrict__ bnm, const float* __restrict__ bnv,
    int relu_flag)
{
    extern __shared__ char smem[];
    __shared__ float s_sc[128], s_sh[128], s_bi[128];
    const int A_HI = 0, A_LO = 32768, B_HI = 65536, B_LO = 98304;
    uint32_t sbase = smem_u32(smem);

    const __nv_bfloat16 *Ah, *Al;
    const __nv_bfloat16* Wimg;
    int K, nchunks, outmode;
    if (which == 0) {
        Ah = g_Hh; Al = g_Hl;
        Wimg = g_w1s + (size_t)layer * 4 * 16384;
        K = 128; nchunks = 1; outmode = 0;
    } else {
        Ah = g_Mh; Al = g_Ml;
        Wimg = g_w2s + (size_t)layer * 4 * 16384;
        K = 256; nchunks = 2; outmode = 1;
    }

    int tid = threadIdx.x, lane = tid & 31, wid = tid >> 5;
    int wm = wid >> 2, wn = wid & 3;      // 2 x 4 warp grid; warp tile 64x32
    int m0 = blockIdx.x * 128;
    int n0 = (which == 0) ? blockIdx.y * 128 : 0;

    if (tid < 128) {
        int col = n0 + tid;
        float sc = bng[col] * rsqrtf(bnv[col] + 1e-5f);
        s_sc[tid] = sc;
        s_sh[tid] = bnb[col] - bnm[col] * sc;
        s_bi[tid] = bias[col];
    }

    float acc[4][4][4];
    #pragma unroll
    for (int i = 0; i < 4; ++i)
        #pragma unroll
        for (int j = 0; j < 4; ++j)
            #pragma unroll
            for (int q = 0; q < 4; ++q) acc[i][j][q] = 0.f;

    // per-lane ldmatrix geometry
    int a_lrow = wm * 64 + (lane & 15);          // + i*16 per m-tile
    int a_x7   = a_lrow & 7;
    int a_lci  = lane >> 4;                      // 0/1: k-chunk select
    int b_nrow = wn * 32 + ((lane >> 4) << 3) + (lane & 7);  // + p*16 per pair
    int b_x7   = b_nrow & 7;
    int b_lci  = (lane >> 3) & 1;

    for (int cc = 0; cc < nchunks; ++cc) {
        if (cc) __syncthreads();
        int k0 = cc << 7;
        // stage A (hi/lo), rows guarded
        for (int it = tid; it < 2048; it += 256) {
            int r = it >> 4, ci = it & 15;
            int gr = m0 + r;
            uint4 vh = make_uint4(0, 0, 0, 0), vl = make_uint4(0, 0, 0, 0);
            if (gr < NN) {
                vh = *(const uint4*)(Ah + (size_t)gr * K + k0 + ci * 8);
                vl = *(const uint4*)(Al + (size_t)gr * K + k0 + ci * 8);
            }
            uint32_t off = r * 256 + ((ci ^ (r & 7)) << 4);
            *(uint4*)(smem + A_HI + off) = vh;
            *(uint4*)(smem + A_LO + off) = vl;
        }
        // stage B (hi/lo) from pre-split weight images
        {
            int img = (which == 0) ? (int)blockIdx.y : cc;
            const __nv_bfloat16* wh = Wimg + ((size_t)img * 2) * 16384;
            const __nv_bfloat16* wl = wh + 16384;
            for (int it = tid; it < 2048; it += 256) {
                int n = it >> 4, ci = it & 15;
                uint32_t off = n * 256 + ((ci ^ (n & 7)) << 4);
                *(uint4*)(smem + B_HI + off) = *(const uint4*)(wh + n * 128 + ci * 8);
                *(uint4*)(smem + B_LO + off) = *(const uint4*)(wl + n * 128 + ci * 8);
            }
        }
        __syncthreads();

        #pragma unroll
        for (int s = 0; s < 8; ++s) {
            uint32_t ah[4][4], al[4][4], bh[4][2], bl[4][2];
            uint32_t acn = (uint32_t)(((s << 1) | a_lci) ^ a_x7);
            #pragma unroll
            for (int i = 0; i < 4; ++i) {
                uint32_t addr = sbase + A_HI + (a_lrow + i * 16) * 256 + (acn << 4);
                ldsm_x4(addr, ah[i][0], ah[i][1], ah[i][2], ah[i][3]);
                ldsm_x4(addr + (A_LO - A_HI), al[i][0], al[i][1], al[i][2], al[i][3]);
            }
            uint32_t bcn = (uint32_t)(((s << 1) | b_lci) ^ b_x7);
            #pragma unroll
            for (int p = 0; p < 2; ++p) {
                uint32_t addr = sbase + B_HI + (b_nrow + p * 16) * 256 + (bcn << 4);
                uint32_t r0, r1, r2, r3;
                ldsm_x4(addr, r0, r1, r2, r3);
                bh[2 * p][0] = r0; bh[2 * p][1] = r1;
                bh[2 * p + 1][0] = r2; bh[2 * p + 1][1] = r3;
                ldsm_x4(addr + (B_LO - B_HI), r0, r1, r2, r3);
                bl[2 * p][0] = r0; bl[2 * p][1] = r1;
                bl[2 * p + 1][0] = r2; bl[2 * p + 1][1] = r3;
            }
            #pragma unroll
            for (int i = 0; i < 4; ++i)
                #pragma unroll
                for (int j = 0; j < 4; ++j)
                    mma16816(acc[i][j], ah[i], bh[j]);
            #pragma unroll
            for (int i = 0; i < 4; ++i)
                #pragma unroll
                for (int j = 0; j < 4; ++j)
                    mma16816(acc[i][j], ah[i], bl[j]);
            #pragma unroll
            for (int i = 0; i < 4; ++i)
                #pragma unroll
                for (int j = 0; j < 4; ++j)
                    mma16816(acc[i][j], al[i], bh[j]);
        }
    }
    __syncthreads();

    // epilogue: bias + BN (+ReLU); outmode 0 -> bf16 hi/lo pairs, 1 -> fp32
    #pragma unroll
    for (int i = 0; i < 4; ++i) {
        int row0 = m0 + wm * 64 + i * 16 + (lane >> 2);
        #pragma unroll
        for (int j = 0; j < 4; ++j) {
            int lc = wn * 32 + j * 8 + (lane & 3) * 2;
            float sc0 = s_sc[lc], sc1 = s_sc[lc + 1];
            float sh0 = s_sh[lc], sh1 = s_sh[lc + 1];
            float bi0 = s_bi[lc], bi1 = s_bi[lc + 1];
            #pragma unroll
            for (int h = 0; h < 2; ++h) {
                int row = row0 + h * 8;
                if (row >= NN) continue;
                float v0 = (acc[i][j][2 * h]     + bi0) * sc0 + sh0;
                float v1 = (acc[i][j][2 * h + 1] + bi1) * sc1 + sh1;
                if (outmode == 0) {
                    v0 = fmaxf(v0, 0.f); v1 = fmaxf(v1, 0.f);
                    __nv_bfloat16 h0 = __float2bfloat16(v0);
                    __nv_bfloat16 h1 = __float2bfloat16(v1);
                    __nv_bfloat16 l0 = __float2bfloat16(v0 - __bfloat162float(h0));
                    __nv_bfloat16 l1 = __float2bfloat16(v1 - __bfloat162float(h1));
                    size_t ob = (size_t)row * 256 + n0 + lc;
                    *(__nv_bfloat162*)(g_Mh + ob) = __nv_bfloat162(h0, h1);
                    *(__nv_bfloat162*)(g_Ml + ob) = __nv_bfloat162(l0, l1);
                } else {
                    if (relu_flag) { v0 = fmaxf(v0, 0.f); v1 = fmaxf(v1, 0.f); }
                    *(float2*)(g_X + (size_t)row * 128 + lc) = make_float2(v0, v1);
                }
            }
        }
    }
}

// ================= pooling + head =================
__device__ __forceinline__ int lb(const int* a, int n, int v) {
    int lo = 0, hi = n;
    while (lo < hi) { int m = (lo + hi) >> 1; if (a[m] < v) lo = m + 1; else hi = m; }
    return lo;
}
__global__ void k_pool(const int* __restrict__ batch,
                       const float* __restrict__ Wp, const float* __restrict__ bp,
                       float* __restrict__ out)
{
    int g = blockIdx.x;
    int lo = lb(batch, NN, g);
    int hi = lb(batch, NN, g + 1);
    int d = threadIdx.x;
    float s = 0.f;
    for (int n = lo; n < hi; ++n) s += g_X[n * DD + d];
    s /= fmaxf((float)(hi - lo), 1.f);
    __shared__ float pooled[DD];
    pooled[d] = s;
    __syncthreads();
    if (d < 10) {
        float o = bp[d];
        #pragma unroll 4
        for (int k = 0; k < DD; ++k) o += pooled[k] * Wp[k * 10 + d];
        out[g * 10 + d] = o;
    }
}

// ================= launch =================
extern "C" void kernel_launch(void* const* d_in, const int* in_sizes, int n_in,
                              void* d_out, int out_size)
{
    const int*   x_atom = (const int*)d_in[0];
    const int*   eidx   = (const int*)d_in[1];
    const int*   eattr  = (const int*)d_in[2];
    const int*   batch  = (const int*)d_in[3];
    const float* aemb   = (const float*)d_in[4];
    const float* bemb   = (const float*)d_in[5];
    const float* eps    = (const float*)d_in[6];
    const float* W1     = (const float*)d_in[7];
    const float* b1     = (const float*)d_in[8];
    const float* g1     = (const float*)d_in[9];
    const float* bt1    = (const float*)d_in[10];
    const float* m1     = (const float*)d_in[11];
    const float* v1     = (const float*)d_in[12];
    const float* W2     = (const float*)d_in[13];
    const float* b2     = (const float*)d_in[14];
    const float* gO     = (const float*)d_in[15];
    const float* btO    = (const float*)d_in[16];
    const float* mO     = (const float*)d_in[17];
    const float* vO     = (const float*)d_in[18];
    const float* Wp     = (const float*)d_in[19];
    const float* bp     = (const float*)d_in[20];
    float* out = (float*)d_out;

    const int SMEMSZ = 131072;
    static int attr_done = 0;
    if (!attr_done) {
        cudaFuncSetAttribute(k_gemm_mma, cudaFuncAttributeMaxDynamicSharedMemorySize, SMEMSZ);
        attr_done = 1;
    }

    // CSR build + encoders + weight preprocessing
    k_zero<<<(NN + 255) / 256, 256>>>();
    k_count<<<(EE + 255) / 256, 256>>>(eidx);
    k_scan<<<1, 1024>>>();
    k_fill<<<(EE + 255) / 256, 256>>>(eidx, eattr);
    k_atom<<<NN / 2, 256>>>(x_atom, aemb);
    k_wconv1<<<LL * 2 * 16384 / 256, 256>>>(W1);
    k_wconv2<<<LL * 2 * 16384 / 256, 256>>>(W2);

    for (int i = 0; i < LL; ++i) {
        k_etab<<<512, 128>>>(bemb + (size_t)i * 3 * 8 * DD);
        k_agg<<<NN / 8, 256>>>(eps, i);
        dim3 grid1((NN + 127) / 128, 2);
        k_gemm_mma<<<grid1, 256, SMEMSZ>>>(0, i,
            b1 + i * 2 * DD, g1 + i * 2 * DD, bt1 + i * 2 * DD,
            m1 + i * 2 * DD, v1 + i * 2 * DD, 1);
        dim3 grid2((NN + 127) / 128, 1);
        k_gemm_mma<<<grid2, 256, SMEMSZ>>>(1, i,
            b2 + i * DD, gO + i * DD, btO + i * DD,
            mO + i * DD, vO + i * DD, (i < LL - 1) ? 1 : 0);
    }

    k_pool<<<GG, 128>>>(batch, Wp, bp, out);
}